// round 5
// baseline (speedup 1.0000x reference)
#include <cuda_runtime.h>

// Problem constants (fixed shapes from reference)
#define RPIX 123904        // 352*352
#define NBV  8             // B*V = 2*4
#define NG   991232        // NBV * RPIX

__global__ __launch_bounds__(256)
void gaussian_adapter_kernel(
    const float* __restrict__ E,       // [NBV,16] extrinsics (4x4 row-major)
    const float* __restrict__ Kmat,    // [NBV,9]  intrinsics (3x3 row-major)
    const float* __restrict__ coords,  // [NG,2]
    const float* __restrict__ depths,  // [NG]
    const float* __restrict__ opac,    // [NG]
    const float* __restrict__ raw,     // [NG,19]
    const float* __restrict__ imgs,    // [NBV,3,RPIX]
    const float* __restrict__ mask,    // [4]
    float* __restrict__ out)           // [32*NG]
{
    const int p  = blockIdx.x * 256 + threadIdx.x;
    const int bv = blockIdx.y;
    if (p >= RPIX) return;
    const size_t g = (size_t)bv * RPIX + p;

    // ---- per-(b,v) camera constants (uniform within block -> L1 broadcast) ----
    const float* Eb = E + bv * 16;
    const float R00 = Eb[0],  R01 = Eb[1],  R02 = Eb[2],  t0 = Eb[3];
    const float R10 = Eb[4],  R11 = Eb[5],  R12 = Eb[6],  t1 = Eb[7];
    const float R20 = Eb[8],  R21 = Eb[9],  R22 = Eb[10], t2 = Eb[11];
    const float fx = Kmat[bv * 9 + 0];
    const float fy = Kmat[bv * 9 + 4];
    const float m0 = mask[0], m1 = mask[1], m2 = mask[2], m3 = mask[3];

    // ---- load raw gaussian record (19 floats) ----
    const float* rg = raw + g * 19;
    float rv[19];
#pragma unroll
    for (int i = 0; i < 19; i++) rv[i] = rg[i];

    // ---- scales = clip(softplus(raw[:3]-4), 0.5, 15) ----
    float sc[3];
#pragma unroll
    for (int i = 0; i < 3; i++) {
        float x  = rv[i] - 4.0f;
        float sp = log1pf(expf(x));
        sc[i] = fminf(fmaxf(sp, 0.5f), 15.0f);
    }

    // ---- rotations = q / (|q| + eps) ----
    float qw = rv[3], qx = rv[4], qy = rv[5], qz = rv[6];
    const float nrm  = sqrtf(qw * qw + qx * qx + qy * qy + qz * qz);
    const float qinv = 1.0f / (nrm + 1e-8f);
    qw *= qinv; qx *= qinv; qy *= qinv; qz *= qinv;

    // ---- quat -> rotation matrix (two_s = 2/|q|^2, exact like reference) ----
    const float qq = qw * qw + qx * qx + qy * qy + qz * qz;
    const float s  = 2.0f / qq;
    const float Q00 = 1.0f - s * (qy * qy + qz * qz);
    const float Q01 = s * (qx * qy - qz * qw);
    const float Q02 = s * (qx * qz + qy * qw);
    const float Q10 = s * (qx * qy + qz * qw);
    const float Q11 = 1.0f - s * (qx * qx + qz * qz);
    const float Q12 = s * (qy * qz - qx * qw);
    const float Q20 = s * (qx * qz - qy * qw);
    const float Q21 = s * (qy * qz + qx * qw);
    const float Q22 = 1.0f - s * (qx * qx + qy * qy);

    // ---- C1 = Q diag(s^2) Q^T (symmetric) ----
    const float v0 = sc[0] * sc[0], v1 = sc[1] * sc[1], v2 = sc[2] * sc[2];
    const float C00 = Q00 * Q00 * v0 + Q01 * Q01 * v1 + Q02 * Q02 * v2;
    const float C01 = Q00 * Q10 * v0 + Q01 * Q11 * v1 + Q02 * Q12 * v2;
    const float C02 = Q00 * Q20 * v0 + Q01 * Q21 * v1 + Q02 * Q22 * v2;
    const float C11 = Q10 * Q10 * v0 + Q11 * Q11 * v1 + Q12 * Q12 * v2;
    const float C12 = Q10 * Q20 * v0 + Q11 * Q21 * v1 + Q12 * Q22 * v2;
    const float C22 = Q20 * Q20 * v0 + Q21 * Q21 * v1 + Q22 * Q22 * v2;

    // ---- A = Rc * C1 ----
    const float A00 = R00 * C00 + R01 * C01 + R02 * C02;
    const float A01 = R00 * C01 + R01 * C11 + R02 * C12;
    const float A02 = R00 * C02 + R01 * C12 + R02 * C22;
    const float A10 = R10 * C00 + R11 * C01 + R12 * C02;
    const float A11 = R10 * C01 + R11 * C11 + R12 * C12;
    const float A12 = R10 * C02 + R11 * C12 + R12 * C22;
    const float A20 = R20 * C00 + R21 * C01 + R22 * C02;
    const float A21 = R20 * C01 + R21 * C11 + R22 * C12;
    const float A22 = R20 * C02 + R21 * C12 + R22 * C22;

    // ---- W = A * Rc^T (world-frame covariance) ----
    const float W00 = A00 * R00 + A01 * R01 + A02 * R02;
    const float W01 = A00 * R10 + A01 * R11 + A02 * R12;
    const float W02 = A00 * R20 + A01 * R21 + A02 * R22;
    const float W10 = A10 * R00 + A11 * R01 + A12 * R02;
    const float W11 = A10 * R10 + A11 * R11 + A12 * R12;
    const float W12 = A10 * R20 + A11 * R21 + A12 * R22;
    const float W20 = A20 * R00 + A21 * R01 + A22 * R02;
    const float W21 = A20 * R10 + A21 * R11 + A22 * R12;
    const float W22 = A20 * R20 + A21 * R21 + A22 * R22;

    // ---- ray direction + means ----
    const float2 c2 = reinterpret_cast<const float2*>(coords)[g];
    const float dx = (c2.x - 0.5f) / fx;
    const float dy = (c2.y - 0.5f) / fy;
    const float dn = 1.0f / sqrtf(dx * dx + dy * dy + 1.0f);
    const float ddx = dx * dn, ddy = dy * dn, ddz = dn;
    const float dir0 = R00 * ddx + R01 * ddy + R02 * ddz;
    const float dir1 = R10 * ddx + R11 * ddy + R12 * ddz;
    const float dir2 = R20 * ddx + R21 * ddy + R22 * ddz;
    const float dep = depths[g];
    const float mx = t0 + dir0 * dep;
    const float my = t1 + dir1 * dep;
    const float mz = t2 + dir2 * dep;

    // ---- spherical harmonics ----
    const float invC0 = 3.5449077018110318f;  // 1 / 0.28209479177387814
    float imv[3];
    imv[0] = imgs[((size_t)bv * 3 + 0) * RPIX + p];
    imv[1] = imgs[((size_t)bv * 3 + 1) * RPIX + p];
    imv[2] = imgs[((size_t)bv * 3 + 2) * RPIX + p];

    float4 Hc[3];
#pragma unroll
    for (int c = 0; c < 3; c++) {
        const float a0 = rv[7 + c * 4 + 0] * m0 + (imv[c] - 0.5f) * invC0;
        const float a1 = rv[7 + c * 4 + 1] * m1;
        const float a2 = rv[7 + c * 4 + 2] * m2;
        const float a3 = rv[7 + c * 4 + 3] * m3;
        // D1 = Rc[perm,:][:,perm], perm=[1,2,0]; sh1 = D1 @ [a1,a2,a3]
        const float h1 = R11 * a1 + R12 * a2 + R10 * a3;
        const float h2 = R21 * a1 + R22 * a2 + R20 * a3;
        const float h3 = R01 * a1 + R02 * a2 + R00 * a3;
        Hc[c] = make_float4(a0, h1, h2, h3);
    }

    // ---- outputs: [means 3N | cov 9N | scales 3N | rot 4N | harm 12N | opac N] ----
    const size_t N = (size_t)NG;
    float* means = out;
    float* cov   = out + 3 * N;
    float* scl   = out + 12 * N;
    float* rot   = out + 15 * N;
    float* harm  = out + 19 * N;
    float* op    = out + 31 * N;

    means[3 * g + 0] = mx;
    means[3 * g + 1] = my;
    means[3 * g + 2] = mz;

    const size_t cb = 9 * g;
    cov[cb + 0] = W00; cov[cb + 1] = W01; cov[cb + 2] = W02;
    cov[cb + 3] = W10; cov[cb + 4] = W11; cov[cb + 5] = W12;
    cov[cb + 6] = W20; cov[cb + 7] = W21; cov[cb + 8] = W22;

    scl[3 * g + 0] = sc[0];
    scl[3 * g + 1] = sc[1];
    scl[3 * g + 2] = sc[2];

    reinterpret_cast<float4*>(rot)[g] = make_float4(qw, qx, qy, qz);

    float4* hp = reinterpret_cast<float4*>(harm + 12 * g);
    hp[0] = Hc[0];
    hp[1] = Hc[1];
    hp[2] = Hc[2];

    op[g] = opac[g];
}

extern "C" void kernel_launch(void* const* d_in, const int* in_sizes, int n_in,
                              void* d_out, int out_size) {
    const float* E      = (const float*)d_in[0];  // extrinsics  [8,16]
    const float* Kmat   = (const float*)d_in[1];  // intrinsics  [8,9]
    const float* coords = (const float*)d_in[2];  // [NG,2]
    const float* depths = (const float*)d_in[3];  // [NG]
    const float* opac   = (const float*)d_in[4];  // [NG]
    const float* raw    = (const float*)d_in[5];  // [NG,19]
    const float* imgs   = (const float*)d_in[6];  // [8,3,RPIX]
    const float* mask   = (const float*)d_in[7];  // [4]
    float* out = (float*)d_out;

    dim3 grid((RPIX + 255) / 256, NBV);           // (484, 8)
    gaussian_adapter_kernel<<<grid, 256>>>(E, Kmat, coords, depths, opac,
                                           raw, imgs, mask, out);
}

// round 7
// speedup vs baseline: 1.8703x; 1.8703x over previous
#include <cuda_runtime.h>

#define RPIX 123904        // 352*352 = 484*256
#define NBV  8             // B*V
#define NG   991232        // NBV * RPIX

// per-warp shared slice: 32 records * 19 floats = 608 floats (2432 B, 16B aligned)
// reused for output staging (cov needs 288, means+scales 192 -> fits)
#define WSLICE 608

__global__ __launch_bounds__(256)
void gaussian_adapter_kernel(
    const float* __restrict__ E,       // [NBV,16]
    const float* __restrict__ Kmat,    // [NBV,9]
    const float* __restrict__ coords,  // [NG,2]
    const float* __restrict__ depths,  // [NG]
    const float* __restrict__ opac,    // [NG]
    const float* __restrict__ raw,     // [NG,19]
    const float* __restrict__ imgs,    // [NBV,3,RPIX]
    const float* __restrict__ mask,    // [4]
    float* __restrict__ out)           // [32*NG]
{
    __shared__ __align__(16) float smem[8 * WSLICE];   // 19456 B

    const int tid  = threadIdx.x;
    const int wid  = tid >> 5;
    const int lane = tid & 31;
    const int bv   = blockIdx.y;
    const int p0   = blockIdx.x * 256 + wid * 32;      // warp's first pixel
    const int p    = p0 + lane;
    const size_t g0 = (size_t)bv * RPIX + p0;          // multiple of 32
    const size_t g  = g0 + lane;

    float* wbuf = smem + wid * WSLICE;
    float4* wbuf4 = reinterpret_cast<float4*>(wbuf);

    // ---- cooperative vectorized load of 32 raw records (152 float4) ----
    const float4* src4 = reinterpret_cast<const float4*>(raw + g0 * 19);
#pragma unroll
    for (int i = 0; i < 5; i++) {
        int idx = lane + i * 32;
        if (idx < 152) wbuf4[idx] = src4[idx];
    }
    __syncwarp();

    // ---- per-lane record from shared (stride 19: conflict-free) ----
    float rv[19];
    const float* myrec = wbuf + lane * 19;
#pragma unroll
    for (int i = 0; i < 19; i++) rv[i] = myrec[i];
    __syncwarp();   // everyone done reading before wbuf is reused for outputs

    // ---- per-(b,v) camera constants (uniform -> broadcast) ----
    const float* Eb = E + bv * 16;
    const float R00 = Eb[0],  R01 = Eb[1],  R02 = Eb[2],  t0 = Eb[3];
    const float R10 = Eb[4],  R11 = Eb[5],  R12 = Eb[6],  t1 = Eb[7];
    const float R20 = Eb[8],  R21 = Eb[9],  R22 = Eb[10], t2 = Eb[11];
    const float fx = Kmat[bv * 9 + 0];
    const float fy = Kmat[bv * 9 + 4];
    const float m0 = mask[0], m1 = mask[1], m2 = mask[2], m3 = mask[3];

    // ---- scales = clip(softplus(raw[:3]-4), 0.5, 15) ----
    float sc[3];
#pragma unroll
    for (int i = 0; i < 3; i++) {
        float x  = rv[i] - 4.0f;
        float sp = log1pf(expf(x));
        sc[i] = fminf(fmaxf(sp, 0.5f), 15.0f);
    }

    // ---- rotations = q / (|q| + eps) ----
    float qw = rv[3], qx = rv[4], qy = rv[5], qz = rv[6];
    const float nrm  = sqrtf(qw * qw + qx * qx + qy * qy + qz * qz);
    const float qinv = 1.0f / (nrm + 1e-8f);
    qw *= qinv; qx *= qinv; qy *= qinv; qz *= qinv;

    // ---- quat -> rotation matrix ----
    const float qq = qw * qw + qx * qx + qy * qy + qz * qz;
    const float s  = 2.0f / qq;
    const float Q00 = 1.0f - s * (qy * qy + qz * qz);
    const float Q01 = s * (qx * qy - qz * qw);
    const float Q02 = s * (qx * qz + qy * qw);
    const float Q10 = s * (qx * qy + qz * qw);
    const float Q11 = 1.0f - s * (qx * qx + qz * qz);
    const float Q12 = s * (qy * qz - qx * qw);
    const float Q20 = s * (qx * qz - qy * qw);
    const float Q21 = s * (qy * qz + qx * qw);
    const float Q22 = 1.0f - s * (qx * qx + qy * qy);

    // ---- C1 = Q diag(s^2) Q^T (symmetric) ----
    const float v0 = sc[0] * sc[0], v1 = sc[1] * sc[1], v2 = sc[2] * sc[2];
    const float C00 = Q00 * Q00 * v0 + Q01 * Q01 * v1 + Q02 * Q02 * v2;
    const float C01 = Q00 * Q10 * v0 + Q01 * Q11 * v1 + Q02 * Q12 * v2;
    const float C02 = Q00 * Q20 * v0 + Q01 * Q21 * v1 + Q02 * Q22 * v2;
    const float C11 = Q10 * Q10 * v0 + Q11 * Q11 * v1 + Q12 * Q12 * v2;
    const float C12 = Q10 * Q20 * v0 + Q11 * Q21 * v1 + Q12 * Q22 * v2;
    const float C22 = Q20 * Q20 * v0 + Q21 * Q21 * v1 + Q22 * Q22 * v2;

    // ---- A = Rc * C1 ----
    const float A00 = R00 * C00 + R01 * C01 + R02 * C02;
    const float A01 = R00 * C01 + R01 * C11 + R02 * C12;
    const float A02 = R00 * C02 + R01 * C12 + R02 * C22;
    const float A10 = R10 * C00 + R11 * C01 + R12 * C02;
    const float A11 = R10 * C01 + R11 * C11 + R12 * C12;
    const float A12 = R10 * C02 + R11 * C12 + R12 * C22;
    const float A20 = R20 * C00 + R21 * C01 + R22 * C02;
    const float A21 = R20 * C01 + R21 * C11 + R22 * C12;
    const float A22 = R20 * C02 + R21 * C12 + R22 * C22;

    // ---- W = A * Rc^T ----
    const float W00 = A00 * R00 + A01 * R01 + A02 * R02;
    const float W01 = A00 * R10 + A01 * R11 + A02 * R12;
    const float W02 = A00 * R20 + A01 * R21 + A02 * R22;
    const float W10 = A10 * R00 + A11 * R01 + A12 * R02;
    const float W11 = A10 * R10 + A11 * R11 + A12 * R12;
    const float W12 = A10 * R20 + A11 * R21 + A12 * R22;
    const float W20 = A20 * R00 + A21 * R01 + A22 * R02;
    const float W21 = A20 * R10 + A21 * R11 + A22 * R12;
    const float W22 = A20 * R20 + A21 * R21 + A22 * R22;

    // ---- ray direction + means ----
    const float2 c2 = reinterpret_cast<const float2*>(coords)[g];
    const float dx = (c2.x - 0.5f) / fx;
    const float dy = (c2.y - 0.5f) / fy;
    const float dn = 1.0f / sqrtf(dx * dx + dy * dy + 1.0f);
    const float ddx = dx * dn, ddy = dy * dn, ddz = dn;
    const float dir0 = R00 * ddx + R01 * ddy + R02 * ddz;
    const float dir1 = R10 * ddx + R11 * ddy + R12 * ddz;
    const float dir2 = R20 * ddx + R21 * ddy + R22 * ddz;
    const float dep = depths[g];
    const float mx = t0 + dir0 * dep;
    const float my = t1 + dir1 * dep;
    const float mz = t2 + dir2 * dep;

    // ---- spherical harmonics ----
    const float invC0 = 3.5449077018110318f;
    float imv[3];
    imv[0] = imgs[((size_t)bv * 3 + 0) * RPIX + p];
    imv[1] = imgs[((size_t)bv * 3 + 1) * RPIX + p];
    imv[2] = imgs[((size_t)bv * 3 + 2) * RPIX + p];

    float4 Hc[3];
#pragma unroll
    for (int c = 0; c < 3; c++) {
        const float a0 = rv[7 + c * 4 + 0] * m0 + (imv[c] - 0.5f) * invC0;
        const float a1 = rv[7 + c * 4 + 1] * m1;
        const float a2 = rv[7 + c * 4 + 2] * m2;
        const float a3 = rv[7 + c * 4 + 3] * m3;
        const float h1 = R11 * a1 + R12 * a2 + R10 * a3;
        const float h2 = R21 * a1 + R22 * a2 + R20 * a3;
        const float h3 = R01 * a1 + R02 * a2 + R00 * a3;
        Hc[c] = make_float4(a0, h1, h2, h3);
    }

    // ---- output regions: [means 3N | cov 9N | scales 3N | rot 4N | harm 12N | opac N] ----
    const size_t N = (size_t)NG;
    float* means = out;
    float* cov   = out + 3 * N;
    float* scl   = out + 12 * N;
    float* rot   = out + 15 * N;
    float* harm  = out + 19 * N;
    float* op    = out + 31 * N;

    // direct vector stores (16B-aligned per element)
    reinterpret_cast<float4*>(rot)[g] = make_float4(qw, qx, qy, qz);
    float4* hp = reinterpret_cast<float4*>(harm + 12 * g);
    hp[0] = Hc[0]; hp[1] = Hc[1]; hp[2] = Hc[2];
    op[g] = opac[g];

    // ---- stage cov (stride 9, conflict-free) then coalesced float4 store ----
    {
        float* cb = wbuf + lane * 9;
        cb[0] = W00; cb[1] = W01; cb[2] = W02;
        cb[3] = W10; cb[4] = W11; cb[5] = W12;
        cb[6] = W20; cb[7] = W21; cb[8] = W22;
        __syncwarp();
        float4* cdst = reinterpret_cast<float4*>(cov + g0 * 9);   // 32*9*4 B region, 16B aligned
#pragma unroll
        for (int i = 0; i < 3; i++) {
            int idx = lane + i * 32;
            if (idx < 72) cdst[idx] = wbuf4[idx];
        }
        __syncwarp();
    }

    // ---- stage means (stride 3) + scales (stride 3) then coalesced stores ----
    {
        float* mb = wbuf + lane * 3;
        mb[0] = mx; mb[1] = my; mb[2] = mz;
        float* sb = wbuf + 96 + lane * 3;
        sb[0] = sc[0]; sb[1] = sc[1]; sb[2] = sc[2];
        __syncwarp();
        float4* mdst = reinterpret_cast<float4*>(means + g0 * 3); // 384 B region, aligned
        float4* sdst = reinterpret_cast<float4*>(scl + g0 * 3);
        if (lane < 24) {
            mdst[lane] = wbuf4[lane];
            sdst[lane] = wbuf4[24 + lane];
        }
        __syncwarp();
    }
}

extern "C" void kernel_launch(void* const* d_in, const int* in_sizes, int n_in,
                              void* d_out, int out_size) {
    const float* E      = (const float*)d_in[0];
    const float* Kmat   = (const float*)d_in[1];
    const float* coords = (const float*)d_in[2];
    const float* depths = (const float*)d_in[3];
    const float* opac   = (const float*)d_in[4];
    const float* raw    = (const float*)d_in[5];
    const float* imgs   = (const float*)d_in[6];
    const float* mask   = (const float*)d_in[7];
    float* out = (float*)d_out;

    dim3 grid(RPIX / 256, NBV);   // (484, 8) exact
    gaussian_adapter_kernel<<<grid, 256>>>(E, Kmat, coords, depths, opac,
                                           raw, imgs, mask, out);
}

// round 11
// speedup vs baseline: 2.1813x; 1.1663x over previous
#include <cuda_runtime.h>

#define RPIX 123904        // 352*352 = 484*256
#define NBV  8             // B*V
#define NG   991232        // NBV * RPIX

// per-warp shared slice: 32 records * 19 floats = 608 floats (2432 B, 16B aligned)
// reused for output staging (cov needs 288, means+scales 192 -> fits)
#define WSLICE 608

__global__ __launch_bounds__(256, 5)
void gaussian_adapter_kernel(
    const float* __restrict__ E,       // [NBV,16]
    const float* __restrict__ Kmat,    // [NBV,9]
    const float* __restrict__ coords,  // [NG,2]
    const float* __restrict__ depths,  // [NG]
    const float* __restrict__ opac,    // [NG]
    const float* __restrict__ raw,     // [NG,19]
    const float* __restrict__ imgs,    // [NBV,3,RPIX]
    const float* __restrict__ mask,    // [4]
    float* __restrict__ out)           // [32*NG]
{
    __shared__ __align__(16) float smem[8 * WSLICE];   // 19456 B

    const int tid  = threadIdx.x;
    const int wid  = tid >> 5;
    const int lane = tid & 31;
    const int bv   = blockIdx.y;
    const int p0   = blockIdx.x * 256 + wid * 32;      // warp's first pixel
    const int p    = p0 + lane;
    const size_t g0 = (size_t)bv * RPIX + p0;          // multiple of 32
    const size_t g  = g0 + lane;

    float* wbuf = smem + wid * WSLICE;
    float4* wbuf4 = reinterpret_cast<float4*>(wbuf);

    // ---- front-batch ALL global loads for max MLP ----
    // cooperative vectorized load of 32 raw records (152 float4)
    const float4* src4 = reinterpret_cast<const float4*>(raw + g0 * 19);
    float4 r4[5];
#pragma unroll
    for (int i = 0; i < 5; i++) {
        int idx = lane + i * 32;
        r4[i] = (idx < 152) ? src4[idx] : make_float4(0.f, 0.f, 0.f, 0.f);
    }
    const float2 c2  = reinterpret_cast<const float2*>(coords)[g];
    const float  dep = depths[g];
    const float  opv = opac[g];
    const float  im0 = imgs[((size_t)bv * 3 + 0) * RPIX + p];
    const float  im1 = imgs[((size_t)bv * 3 + 1) * RPIX + p];
    const float  im2 = imgs[((size_t)bv * 3 + 2) * RPIX + p];

#pragma unroll
    for (int i = 0; i < 5; i++) {
        int idx = lane + i * 32;
        if (idx < 152) wbuf4[idx] = r4[i];
    }
    __syncwarp();

    // ---- per-lane scalar part of record (7 floats) ----
    const float* myrec = wbuf + lane * 19;
    float rv0 = myrec[0], rv1 = myrec[1], rv2 = myrec[2];
    float qw  = myrec[3], qx  = myrec[4], qy = myrec[5], qz = myrec[6];

    // ---- per-(b,v) camera constants (uniform -> broadcast) ----
    const float* Eb = E + bv * 16;
    const float R00 = Eb[0],  R01 = Eb[1],  R02 = Eb[2],  t0 = Eb[3];
    const float R10 = Eb[4],  R11 = Eb[5],  R12 = Eb[6],  t1 = Eb[7];
    const float R20 = Eb[8],  R21 = Eb[9],  R22 = Eb[10], t2 = Eb[11];
    const float fx = Kmat[bv * 9 + 0];
    const float fy = Kmat[bv * 9 + 4];

    // ---- scales = clip(softplus(raw[:3]-4), 0.5, 15)  (fast-math path, clip hides err) ----
    float sc0, sc1, sc2;
    {
        float s0 = __logf(1.0f + __expf(rv0 - 4.0f));
        float s1 = __logf(1.0f + __expf(rv1 - 4.0f));
        float s2 = __logf(1.0f + __expf(rv2 - 4.0f));
        sc0 = fminf(fmaxf(s0, 0.5f), 15.0f);
        sc1 = fminf(fmaxf(s1, 0.5f), 15.0f);
        sc2 = fminf(fmaxf(s2, 0.5f), 15.0f);
    }

    // ---- rotations = q / (|q| + eps) ----
    const float nrm  = sqrtf(qw * qw + qx * qx + qy * qy + qz * qz);
    const float qinv = 1.0f / (nrm + 1e-8f);
    qw *= qinv; qx *= qinv; qy *= qinv; qz *= qinv;

    // ---- quat -> rotation matrix ----
    const float qq = qw * qw + qx * qx + qy * qy + qz * qz;
    const float s  = 2.0f / qq;
    const float Q00 = 1.0f - s * (qy * qy + qz * qz);
    const float Q01 = s * (qx * qy - qz * qw);
    const float Q02 = s * (qx * qz + qy * qw);
    const float Q10 = s * (qx * qy + qz * qw);
    const float Q11 = 1.0f - s * (qx * qx + qz * qz);
    const float Q12 = s * (qy * qz - qx * qw);
    const float Q20 = s * (qx * qz - qy * qw);
    const float Q21 = s * (qy * qz + qx * qw);
    const float Q22 = 1.0f - s * (qx * qx + qy * qy);

    // ---- C1 = Q diag(s^2) Q^T (symmetric) ----
    const float v0 = sc0 * sc0, v1 = sc1 * sc1, v2 = sc2 * sc2;
    const float C00 = Q00 * Q00 * v0 + Q01 * Q01 * v1 + Q02 * Q02 * v2;
    const float C01 = Q00 * Q10 * v0 + Q01 * Q11 * v1 + Q02 * Q12 * v2;
    const float C02 = Q00 * Q20 * v0 + Q01 * Q21 * v1 + Q02 * Q22 * v2;
    const float C11 = Q10 * Q10 * v0 + Q11 * Q11 * v1 + Q12 * Q12 * v2;
    const float C12 = Q10 * Q20 * v0 + Q11 * Q21 * v1 + Q12 * Q22 * v2;
    const float C22 = Q20 * Q20 * v0 + Q21 * Q21 * v1 + Q22 * Q22 * v2;

    // ---- A = Rc * C1 ----
    const float A00 = R00 * C00 + R01 * C01 + R02 * C02;
    const float A01 = R00 * C01 + R01 * C11 + R02 * C12;
    const float A02 = R00 * C02 + R01 * C12 + R02 * C22;
    const float A10 = R10 * C00 + R11 * C01 + R12 * C02;
    const float A11 = R10 * C01 + R11 * C11 + R12 * C12;
    const float A12 = R10 * C02 + R11 * C12 + R12 * C22;
    const float A20 = R20 * C00 + R21 * C01 + R22 * C02;
    const float A21 = R20 * C01 + R21 * C11 + R22 * C12;
    const float A22 = R20 * C02 + R21 * C12 + R22 * C22;

    // ---- W = A * Rc^T ----
    const float W00 = A00 * R00 + A01 * R01 + A02 * R02;
    const float W01 = A00 * R10 + A01 * R11 + A02 * R12;
    const float W02 = A00 * R20 + A01 * R21 + A02 * R22;
    const float W10 = A10 * R00 + A11 * R01 + A12 * R02;
    const float W11 = A10 * R10 + A11 * R11 + A12 * R12;
    const float W12 = A10 * R20 + A11 * R21 + A12 * R22;
    const float W20 = A20 * R00 + A21 * R01 + A22 * R02;
    const float W21 = A20 * R10 + A21 * R11 + A22 * R12;
    const float W22 = A20 * R20 + A21 * R21 + A22 * R22;

    // ---- ray direction + means ----
    const float dx = (c2.x - 0.5f) / fx;
    const float dy = (c2.y - 0.5f) / fy;
    const float dn = 1.0f / sqrtf(dx * dx + dy * dy + 1.0f);
    const float ddx = dx * dn, ddy = dy * dn, ddz = dn;
    const float mx = t0 + (R00 * ddx + R01 * ddy + R02 * ddz) * dep;
    const float my = t1 + (R10 * ddx + R11 * ddy + R12 * ddz) * dep;
    const float mz = t2 + (R20 * ddx + R21 * ddy + R22 * ddz) * dep;

    // ---- output regions: [means 3N | cov 9N | scales 3N | rot 4N | harm 12N | opac N] ----
    const size_t N = (size_t)NG;
    float* means = out;
    float* cov   = out + 3 * N;
    float* scl   = out + 12 * N;
    float* rot   = out + 15 * N;
    float* harm  = out + 19 * N;
    float* op    = out + 31 * N;

    // direct vector stores (16B-aligned per element)
    reinterpret_cast<float4*>(rot)[g] = make_float4(qw, qx, qy, qz);
    op[g] = opv;

    // ---- spherical harmonics: read SH coeffs from smem only now (low reg pressure) ----
    {
        const float m0 = mask[0], m1 = mask[1], m2 = mask[2], m3 = mask[3];
        const float invC0 = 3.5449077018110318f;
        const float imv[3] = { im0, im1, im2 };
        float4* hp = reinterpret_cast<float4*>(harm + 12 * g);
#pragma unroll
        for (int c = 0; c < 3; c++) {
            const float a0 = myrec[7 + c * 4 + 0] * m0 + (imv[c] - 0.5f) * invC0;
            const float a1 = myrec[7 + c * 4 + 1] * m1;
            const float a2 = myrec[7 + c * 4 + 2] * m2;
            const float a3 = myrec[7 + c * 4 + 3] * m3;
            const float h1 = R11 * a1 + R12 * a2 + R10 * a3;
            const float h2 = R21 * a1 + R22 * a2 + R20 * a3;
            const float h3 = R01 * a1 + R02 * a2 + R00 * a3;
            hp[c] = make_float4(a0, h1, h2, h3);
        }
    }
    __syncwarp();   // all lanes done reading smem records; wbuf reusable

    // ---- stage cov (stride 9, conflict-free) then coalesced float4 store ----
    {
        float* cb = wbuf + lane * 9;
        cb[0] = W00; cb[1] = W01; cb[2] = W02;
        cb[3] = W10; cb[4] = W11; cb[5] = W12;
        cb[6] = W20; cb[7] = W21; cb[8] = W22;
        __syncwarp();
        float4* cdst = reinterpret_cast<float4*>(cov + g0 * 9);   // 1152 B region, aligned
#pragma unroll
        for (int i = 0; i < 3; i++) {
            int idx = lane + i * 32;
            if (idx < 72) cdst[idx] = wbuf4[idx];
        }
        __syncwarp();
    }

    // ---- stage means (stride 3) + scales (stride 3) then coalesced stores ----
    {
        float* mb = wbuf + lane * 3;
        mb[0] = mx; mb[1] = my; mb[2] = mz;
        float* sb = wbuf + 96 + lane * 3;
        sb[0] = sc0; sb[1] = sc1; sb[2] = sc2;
        __syncwarp();
        float4* mdst = reinterpret_cast<float4*>(means + g0 * 3); // 384 B region, aligned
        float4* sdst = reinterpret_cast<float4*>(scl + g0 * 3);
        if (lane < 24) {
            mdst[lane] = wbuf4[lane];
            sdst[lane] = wbuf4[24 + lane];
        }
        __syncwarp();
    }
}

extern "C" void kernel_launch(void* const* d_in, const int* in_sizes, int n_in,
                              void* d_out, int out_size) {
    const float* E      = (const float*)d_in[0];
    const float* Kmat   = (const float*)d_in[1];
    const float* coords = (const float*)d_in[2];
    const float* depths = (const float*)d_in[3];
    const float* opac   = (const float*)d_in[4];
    const float* raw    = (const float*)d_in[5];
    const float* imgs   = (const float*)d_in[6];
    const float* mask   = (const float*)d_in[7];
    float* out = (float*)d_out;

    dim3 grid(RPIX / 256, NBV);   // (484, 8) exact
    gaussian_adapter_kernel<<<grid, 256>>>(E, Kmat, coords, depths, opac,
                                           raw, imgs, mask, out);
}